// round 16
// baseline (speedup 1.0000x reference)
#include <cuda_runtime.h>
#include <math.h>

#define BB 4096
#define TT 128
#define SS 12288              // 3 * BB channel-chains
#define NSLOT 126             // loss slots u = t-2, t in [2,127]
#define NG 125                // history slots, m = t-2 (filtered) / t-3 (prediction)

// shared memory layout (floats)
#define SZ_Z   (384 * 33)             // z staged: [k=t*3+ch][lane] padded
#define SZ_SV  (3 * NSLOT * 32)       // Sv table: [ch][u][lane]
#define SZ_D   (NG * 96)              // Pc filtered history: [m][tid]
#define SZ_SP  (NG * 96)              // spv prediction history: [m][tid]
#define SMEM_FLOATS (SZ_Z + SZ_SV + SZ_D + SZ_SP)
#define SMEM_BYTES  (SMEM_FLOATS * 4)

// ---------------- device scratch (no allocations allowed) ----------------
__device__ float4 g_F[NG * SS];    // filtered p,v,Pa,Pb      (slot m = t-2)
__device__ float4 g_P[NG * SS];    // prediction ap,bp,cpv,g  (slot m = t-3)
__device__ float  g_bsum[128];     // per-block partials
__device__ unsigned int g_cnt;     // last-block gate (self-resetting)

static __device__ __forceinline__ float sigmoidf_(float x) {
    return 1.0f / (1.0f + expf(-x));
}
static __device__ __forceinline__ float tanh_fast(float x) {
    float y; asm("tanh.approx.f32 %0, %1;" : "=f"(y) : "f"(x)); return y;
}
static __device__ __forceinline__ float rcp_fast(float x) {
    float y; asm("rcp.approx.f32 %0, %1;" : "=f"(y) : "f"(x)); return y;
}

__global__ void __launch_bounds__(96, 1)
k_all(const float* __restrict__ params,
      const float* __restrict__ covp,
      const float* __restrict__ init_states,
      const float* __restrict__ zin,
      float* __restrict__ out)
{
    extern __shared__ float smem[];
    float* sZ  = smem;                               // [384][33]
    float* sSv = smem + SZ_Z;                        // [3][126][32]
    float* sD  = smem + SZ_Z + SZ_SV;                // [125][96]  Pc filtered
    float* sSp = smem + SZ_Z + SZ_SV + SZ_D;         // [125][96]  spv prediction
    __shared__ bool sLast;

    const int tid  = threadIdx.x;
    const int ch   = tid >> 5;           // warp index = channel
    const int lane = tid & 31;
    const int b    = (blockIdx.x << 5) + lane;
    const int s    = ch * BB + b;        // column in g_F / g_P

    // ---------- stage this block's measurements into smem (coalesced) ----------
    {
        const float* zblk = zin + (size_t)(blockIdx.x << 5) * (TT * 3);
#pragma unroll 4
        for (int lb = 0; lb < 32; lb++) {
            const float4 vz = reinterpret_cast<const float4*>(zblk + lb * 384)[tid];
            const int k = tid << 2;
            sZ[(k + 0) * 33 + lb] = vz.x;
            sZ[(k + 1) * 33 + lb] = vz.y;
            sZ[(k + 2) * 33 + lb] = vz.z;
            sZ[(k + 3) * 33 + lb] = vz.w;
        }
    }

    const float DT     = 1.0f / 120.0f;
    const float TWO_PI = 6.28318530717958647692f;
    const float INV2PI = 0.15915494309189533577f;
    const float FOLD   = 4.71238898038468985769f;

    const float friction = (tanhf(params[0]) + 1.0f) * 0.01f;
    const float damping  = (tanhf(params[1]) + 1.0f) * 0.01f;

    const bool  ang   = (ch == 2);
    const float r     = sigmoidf_(covp[ch]);
    const float qp    = sigmoidf_(covp[ang ? 5 : 3]);
    const float qv    = sigmoidf_(covp[ang ? 6 : 4]);
    const float gd    = 1.0f - DT * damping;
    const float Df_c    = ang ? 0.0f : DT * friction;
    const float Ag_c    = ang ? 0.0f : DT * friction * 100.0f;
    const float gdmAg_c = gd - Ag_c;
    const float wTP     = ang ? TWO_PI : 0.0f;
    const float FOLD_c  = ang ? FOLD : 3.0e38f;

    float p, v, Pa = 0.01f, Pb = 0.0f, Pc = 0.01f;
    {
        const int pi = ang ? 4 : ch;
        const int vi = ang ? 5 : (ch + 2);
        p = init_states[b * 6 + pi];
        v = init_states[b * 6 + vi];
    }

    __syncthreads();   // z staged

#define ZLDS(t) sZ[((t) * 3 + ch) * 33 + lane]

    // =========================== FORWARD EKF ===========================
    // o_* export the prediction quantities of the current step for storage.
    float o_ap, o_bp, o_cpv, o_g, o_spv;

#define FW_MATH(zc)                                                              \
    do {                                                                         \
        const float th   = tanh_fast(100.0f * v);                                \
        o_spv = __fmaf_rn(-Df_c, th, gd * v);                                    \
        o_g   = __fmaf_rn(Ag_c, th * th, gdmAg_c);                               \
        const float spp_ = __fmaf_rn(DT, v, p);                                  \
        const float bdc  = __fmaf_rn(DT, Pc, Pb);                                \
        o_ap  = __fmaf_rn(DT, Pb + bdc, Pa) + qp;                                \
        o_bp  = o_g * bdc;                                                       \
        o_cpv = __fmaf_rn(o_g * o_g, Pc, qv);                                    \
        float innov = (zc) - spp_;                                               \
        innov = __fmaf_rn(-wTP, rintf(innov * INV2PI), innov);                   \
        const float inv = rcp_fast(o_ap + r);                                    \
        const float K0  = o_ap * inv;                                            \
        const float K1  = o_bp * inv;                                            \
        p  = __fmaf_rn(K0, innov, spp_);                                         \
        v  = __fmaf_rn(K1, innov, o_spv);                                        \
        Pa = r * K0;                                                             \
        Pb = r * K1;                                                             \
        Pc = __fmaf_rn(-K1, o_bp, o_cpv);                                        \
    } while (0)

    {
        float zcur = ZLDS(0);
        // t = 0, 1 peeled (no stores)
        {
            const float znext = ZLDS(1);
            FW_MATH(zcur);
            zcur = znext;
        }
        {
            const float znext = ZLDS(2);
            FW_MATH(zcur);
            zcur = znext;
        }
        // t = 2 peeled: filtered store only (prediction belongs to slot -1)
        {
            const float znext = ZLDS(3);
            FW_MATH(zcur);
            g_F[0 * SS + s] = make_float4(p, v, Pa, Pb);
            sD[0 * 96 + tid] = Pc;
            zcur = znext;
        }
        // t in [3,126]: prediction -> slot t-3, filtered -> slot t-2 (no guards)
#pragma unroll 4
        for (int t = 3; t <= 126; t++) {
            const float znext = ZLDS(t + 1);
            FW_MATH(zcur);
            const int mp = t - 3;
            g_P[mp * SS + s] = make_float4(o_ap, o_bp, o_cpv, o_g);
            sSp[mp * 96 + tid] = o_spv;
            const int mf = t - 2;
            g_F[mf * SS + s] = make_float4(p, v, Pa, Pb);
            sD[mf * 96 + tid] = Pc;
            zcur = znext;
        }
        // t = 127 peeled: prediction store only (slot 124)
        FW_MATH(zcur);
        g_P[124 * SS + s] = make_float4(o_ap, o_bp, o_cpv, o_g);
        sSp[124 * 96 + tid] = o_spv;
    }
#undef FW_MATH

    // loss at t = 127 (smoothed == filtered)
    float acc;
    {
        const float zf = ZLDS(TT - 1);
        float e = zf - p;
        e = (e >  FOLD_c) ? e - TWO_PI : e;
        e = (e < -FOLD_c) ? e + TWO_PI : e;
        const float Sv = Pa + r;
        sSv[(ch * NSLOT + 125) * 32 + lane] = Sv;
        acc = Sv * e * e;
    }

    // =========================== BACKWARD RTS (prediction reused, not recomputed) ===========================
    float c0 = p, c1 = v, Q00 = Pa, Q01 = Pb, Q11 = Pc;

    float4 Fa[4], Fb[4];       // filtered p,v,Pa,Pb
    float4 Pp4a[4], Pp4b[4];   // prediction ap,bp,cpv,g
    float  Ca[4], Cb[4], Za[4], Zb[4];
#pragma unroll
    for (int j = 0; j < 4; j++) {
        Fa[j] = make_float4(0,0,0,0); Fb[j] = Fa[j];
        Pp4a[j] = Fa[j]; Pp4b[j] = Fa[j];
        Ca[j] = Cb[j] = Za[j] = Zb[j] = 0.0f;
    }

#define BW_LOADC(F_, P_, C_, Z_, tq)                                             \
    do { if ((tq) >= 2) {                                                        \
        const int _m = (tq) - 2;                                                 \
        F_ = g_F[_m * SS + s];                                                   \
        P_ = g_P[_m * SS + s];                                                   \
        C_ = sD[_m * 96 + tid];                                                  \
        Z_ = ZLDS(tq);                                                           \
    } } while (0)

#define BW_STEP(Fv, Pv, Cv, Zv, tc)                                              \
    do { if ((tc) >= 2) {                                                        \
        const float fp = (Fv).x, fv = (Fv).y, fa = (Fv).z, fb = (Fv).w;          \
        const float fc = (Cv);                                                   \
        const float ap  = (Pv).x, bp = (Pv).y, cpv = (Pv).z, g_ = (Pv).w;        \
        const float spv_ = sSp[((tc) - 2) * 96 + tid];                           \
        const float spp_ = __fmaf_rn(DT, fv, fp);                                \
        const float w0   = __fmaf_rn(DT, fc, fb);                                \
        const float idet = rcp_fast(__fmaf_rn(ap, cpv, -bp * bp));               \
        const float cpvI = cpv * idet;                                           \
        const float bpI  = bp  * idet;                                           \
        const float apI  = ap  * idet;                                           \
        const float u0 = __fmaf_rn(DT, fb, fa);                                  \
        const float u1 = g_ * fb;                                                \
        const float w1 = g_ * fc;                                                \
        const float G00 = __fmaf_rn(u0, cpvI, -u1 * bpI);                        \
        const float G01 = __fmaf_rn(u1, apI,  -u0 * bpI);                        \
        const float G10 = __fmaf_rn(w0, cpvI, -w1 * bpI);                        \
        const float G11 = __fmaf_rn(w1, apI,  -w0 * bpI);                        \
        const float ds0 = c0 - spp_;                                             \
        const float ds1 = c1 - spv_;                                             \
        const float ssp = __fmaf_rn(G00, ds0, __fmaf_rn(G01, ds1, fp));          \
        const float ssv = __fmaf_rn(G10, ds0, __fmaf_rn(G11, ds1, fv));          \
        const float E00 = Q00 - ap;                                              \
        const float E01 = Q01 - bp;                                              \
        const float E11 = Q11 - cpv;                                             \
        const float M00 = __fmaf_rn(G00, E00, G01 * E01);                        \
        const float M01 = __fmaf_rn(G00, E01, G01 * E11);                        \
        const float M10 = __fmaf_rn(G10, E00, G11 * E01);                        \
        const float M11 = __fmaf_rn(G10, E01, G11 * E11);                        \
        const float nQ00 = __fmaf_rn(M00, G00, __fmaf_rn(M01, G01, fa));         \
        const float nQ01 = __fmaf_rn(M00, G10, __fmaf_rn(M01, G11, fb));         \
        const float nQ11 = __fmaf_rn(M10, G10, __fmaf_rn(M11, G11, fc));         \
        c0 = ssp; c1 = ssv; Q00 = nQ00; Q01 = nQ01; Q11 = nQ11;                  \
        const float Sv = nQ00 + r;                                               \
        float e = (Zv) - ssp;                                                    \
        e = (e >  FOLD_c) ? e - TWO_PI : e;                                      \
        e = (e < -FOLD_c) ? e + TWO_PI : e;                                      \
        acc = __fmaf_rn(Sv * e, e, acc);                                         \
        sSv[(ch * NSLOT + ((tc) - 2)) * 32 + lane] = Sv;                         \
    } } while (0)

#pragma unroll
    for (int j = 0; j < 4; j++) BW_LOADC(Fa[j], Pp4a[j], Ca[j], Za[j], 126 - j);
#pragma unroll
    for (int j = 0; j < 4; j++) BW_LOADC(Fb[j], Pp4b[j], Cb[j], Zb[j], 122 - j);

    // main loop: 15 x 8 = 120 steps, t = 126 down to 7 (guards trim nothing here)
    for (int ii = 0; ii < 15; ii++) {
        const int head_a = 126 - 8 * ii;
        const int pre_a  = head_a - 8;
#pragma unroll
        for (int j = 0; j < 4; j++) {
            const float4 Fv = Fa[j], Pv = Pp4a[j];
            const float  Cv = Ca[j], Zv = Za[j];
            BW_LOADC(Fa[j], Pp4a[j], Ca[j], Za[j], pre_a - j);
            BW_STEP(Fv, Pv, Cv, Zv, head_a - j);
        }
        const int head_b = head_a - 4;
        const int pre_b  = head_b - 8;
#pragma unroll
        for (int j = 0; j < 4; j++) {
            const float4 Fv = Fb[j], Pv = Pp4b[j];
            const float  Cv = Cb[j], Zv = Zb[j];
            BW_LOADC(Fb[j], Pp4b[j], Cb[j], Zb[j], pre_b - j);
            BW_STEP(Fv, Pv, Cv, Zv, head_b - j);
        }
    }
    // tail: t = 6,5,4,3 from bank A, t = 2 from bank B (loaded during last iteration)
    BW_STEP(Fa[0], Pp4a[0], Ca[0], Za[0], 6);
    BW_STEP(Fa[1], Pp4a[1], Ca[1], Za[1], 5);
    BW_STEP(Fa[2], Pp4a[2], Ca[2], Za[2], 4);
    BW_STEP(Fa[3], Pp4a[3], Ca[3], Za[3], 3);
    BW_STEP(Fb[0], Pp4b[0], Cb[0], Zb[0], 2);
#undef BW_LOADC
#undef BW_STEP
#undef ZLDS

    // =========================== in-block combine ===========================
    __syncthreads();

    float total = acc;
    // 126*32 = 4032 = 42 * 96 exactly
    for (int idx = tid; idx < NSLOT * 32; idx += 96) {
        const int u = idx >> 5;
        const int l = idx & 31;
        total += sSv[(0 * NSLOT + u) * 32 + l]
               * sSv[(1 * NSLOT + u) * 32 + l]
               * sSv[(2 * NSLOT + u) * 32 + l];
    }
    // warp-level reduce, then 3 partials via smem
#pragma unroll
    for (int k = 16; k > 0; k >>= 1)
        total += __shfl_xor_sync(0xffffffffu, total, k);
    __syncthreads();            // all Sv reads done; reuse smem front as scratch
    if (lane == 0) sSv[ch] = total;
    __syncthreads();
    if (tid == 0) g_bsum[blockIdx.x] = sSv[0] + sSv[1] + sSv[2];
    __threadfence();
    if (tid == 0) {
        const unsigned int old = atomicInc(&g_cnt, 127u);
        sLast = (old == 127u);
    }
    __syncthreads();

    // last block: deterministic final reduce of 128 partials
    if (sLast && tid < 32) {
        __threadfence();
        double ds = 0.0;
#pragma unroll
        for (int j = 0; j < 4; j++) ds += (double)g_bsum[tid * 4 + j];
#pragma unroll
        for (int k = 16; k > 0; k >>= 1)
            ds += __shfl_xor_sync(0xffffffffu, ds, k);
        if (tid == 0) out[0] = (float)ds;
    }
}

// ---------------- launch ----------------
extern "C" void kernel_launch(void* const* d_in, const int* in_sizes, int n_in,
                              void* d_out, int out_size) {
    const float* params = nullptr;
    const float* covp   = nullptr;
    const float* init   = nullptr;
    const float* meas   = nullptr;

    for (int i = 0; i < n_in; i++) {
        if      (in_sizes[i] == 4)            params = (const float*)d_in[i];
        else if (in_sizes[i] == 7)            covp   = (const float*)d_in[i];
        else if (in_sizes[i] == BB * 6)       init   = (const float*)d_in[i];
        else if (in_sizes[i] == BB * TT * 3)  meas   = (const float*)d_in[i];
    }
    if (!params && n_in > 0) params = (const float*)d_in[0];
    if (!covp   && n_in > 1) covp   = (const float*)d_in[1];
    if (!init   && n_in > 2) init   = (const float*)d_in[2];
    if (!meas   && n_in > 3) meas   = (const float*)d_in[3];

    static int smem_set = 0;
    if (!smem_set) {
        cudaFuncSetAttribute(k_all, cudaFuncAttributeMaxDynamicSharedMemorySize,
                             SMEM_BYTES);
        smem_set = 1;
    }

    k_all<<<128, 96, SMEM_BYTES>>>(params, covp, init, meas, (float*)d_out);
}

// round 17
// speedup vs baseline: 1.1772x; 1.1772x over previous
#include <cuda_runtime.h>
#include <math.h>

#define BB 4096
#define TT 128
#define SS 12288              // 3 * BB channel-chains
#define NSLOT 126             // loss slots u = t-2, t in [2,127]
#define NG 125                // filtered-history slots, t in [2,126], m = t-2

// shared memory layout (floats)
#define SZ_Z   (384 * 33)             // z staged: [k=t*3+ch][lane] padded
#define SZ_SV  (3 * NSLOT * 32)       // Sv table: [ch][u][lane]
#define SZ_D   (NG * 96)              // Pc history: [m][tid]
#define SMEM_FLOATS (SZ_Z + SZ_SV + SZ_D)
#define SMEM_BYTES  (SMEM_FLOATS * 4)

// ---------------- device scratch (no allocations allowed) ----------------
__device__ float4 g_F[NG * SS];    // filtered p,v,Pa,Pb
__device__ float  g_bsum[128];     // per-block partials
__device__ unsigned int g_cnt;     // last-block gate (self-resetting)

static __device__ __forceinline__ float sigmoidf_(float x) {
    return 1.0f / (1.0f + expf(-x));
}
static __device__ __forceinline__ float tanh_fast(float x) {
    float y; asm("tanh.approx.f32 %0, %1;" : "=f"(y) : "f"(x)); return y;
}
static __device__ __forceinline__ float rcp_fast(float x) {
    float y; asm("rcp.approx.f32 %0, %1;" : "=f"(y) : "f"(x)); return y;
}

__global__ void __launch_bounds__(96, 1)
k_all(const float* __restrict__ params,
      const float* __restrict__ covp,
      const float* __restrict__ init_states,
      const float* __restrict__ zin,
      float* __restrict__ out)
{
    extern __shared__ float smem[];
    float* sZ  = smem;                   // [384][33]
    float* sSv = smem + SZ_Z;            // [3][126][32]
    float* sD  = smem + SZ_Z + SZ_SV;    // [125][96]
    __shared__ bool sLast;

    const int tid  = threadIdx.x;
    const int ch   = tid >> 5;           // warp index = channel
    const int lane = tid & 31;
    const int b    = (blockIdx.x << 5) + lane;
    const int s    = ch * BB + b;        // column in g_F

    // ---------- stage this block's measurements into smem (coalesced) ----------
    {
        const float* zblk = zin + (size_t)(blockIdx.x << 5) * (TT * 3);
#pragma unroll 4
        for (int lb = 0; lb < 32; lb++) {
            const float4 vz = reinterpret_cast<const float4*>(zblk + lb * 384)[tid];
            const int k = tid << 2;
            sZ[(k + 0) * 33 + lb] = vz.x;
            sZ[(k + 1) * 33 + lb] = vz.y;
            sZ[(k + 2) * 33 + lb] = vz.z;
            sZ[(k + 3) * 33 + lb] = vz.w;
        }
    }

    const float DT     = 1.0f / 120.0f;
    const float TWO_PI = 6.28318530717958647692f;
    const float INV2PI = 0.15915494309189533577f;
    const float FOLD   = 4.71238898038468985769f;

    const float friction = (tanhf(params[0]) + 1.0f) * 0.01f;
    const float damping  = (tanhf(params[1]) + 1.0f) * 0.01f;

    const bool  ang   = (ch == 2);
    const float r     = sigmoidf_(covp[ch]);
    const float qp    = sigmoidf_(covp[ang ? 5 : 3]);
    const float qv    = sigmoidf_(covp[ang ? 6 : 4]);
    const float qpr   = qp + r;                       // hoisted fold
    const float gd    = 1.0f - DT * damping;
    // channel-selected constants -> one uniform branch-free code path
    const float Df_c    = ang ? 0.0f : DT * friction;
    const float Ag_c    = ang ? 0.0f : DT * friction * 100.0f;
    const float gdmAg_c = gd - Ag_c;
    const float wTP     = ang ? TWO_PI : 0.0f;        // innovation wrap gain
    const float FOLD_c  = ang ? FOLD : 3.0e38f;       // fold sentinel

    float p, v, Pa = 0.01f, Pb = 0.0f, Pc = 0.01f;
    {
        const int pi = ang ? 4 : ch;
        const int vi = ang ? 5 : (ch + 2);
        p = init_states[b * 6 + pi];
        v = init_states[b * 6 + vi];
    }

    __syncthreads();   // z staged

#define ZLDS(t) sZ[((t) * 3 + ch) * 33 + lane]

    // =========================== FORWARD EKF (branch-free step, ap-free) ===========================
#define FW_MATH(zc)                                                              \
    do {                                                                         \
        const float th   = tanh_fast(100.0f * v);                                \
        const float spv_ = __fmaf_rn(-Df_c, th, gd * v);                         \
        const float g_   = __fmaf_rn(Ag_c, th * th, gdmAg_c);                    \
        const float spp_ = __fmaf_rn(DT, v, p);                                  \
        const float bdc  = __fmaf_rn(DT, Pc, Pb);                                \
        const float S_   = __fmaf_rn(DT, Pb + bdc, Pa) + qpr;                    \
        const float bp   = g_ * bdc;                                             \
        const float cpv  = __fmaf_rn(g_ * g_, Pc, qv);                           \
        float innov = (zc) - spp_;                                               \
        innov = __fmaf_rn(-wTP, rintf(innov * INV2PI), innov);                   \
        const float inv = rcp_fast(S_);                                          \
        const float K0  = __fmaf_rn(-r, inv, 1.0f);                              \
        const float K1  = bp * inv;                                              \
        p  = __fmaf_rn(K0, innov, spp_);                                         \
        v  = __fmaf_rn(K1, innov, spv_);                                         \
        Pa = r * K0;                                                             \
        Pb = r * K1;                                                             \
        Pc = __fmaf_rn(-K1, bp, cpv);                                            \
    } while (0)

    {
        float zcur = ZLDS(0);
        // t = 0, 1 peeled (no history store)
        {
            const float znext = ZLDS(1);
            FW_MATH(zcur);
            zcur = znext;
        }
        {
            const float znext = ZLDS(2);
            FW_MATH(zcur);
            zcur = znext;
        }
        // t in [2,126]: store always (no guard)
#pragma unroll 5
        for (int t = 2; t <= 126; t++) {
            const float znext = ZLDS(t + 1);
            FW_MATH(zcur);
            const int m_ = t - 2;
            g_F[m_ * SS + s] = make_float4(p, v, Pa, Pb);
            sD[m_ * 96 + tid] = Pc;
            zcur = znext;
        }
        // t = 127 peeled (no store)
        FW_MATH(zcur);
    }
#undef FW_MATH

    // loss at t = 127 (smoothed == filtered)
    float acc;
    {
        const float zf = ZLDS(TT - 1);
        float e = zf - p;
        e = (e >  FOLD_c) ? e - TWO_PI : e;
        e = (e < -FOLD_c) ? e + TWO_PI : e;
        const float Sv = Pa + r;
        sSv[(ch * NSLOT + 125) * 32 + lane] = Sv;
        acc = Sv * e * e;
    }

    // =========================== BACKWARD RTS (branch-free, clamped prefetch) ===========================
    float c0 = p, c1 = v, Q00 = Pa, Q01 = Pb, Q11 = Pc;

    float4 Fa[4], Fb[4];
    float  Ca[4], Cb[4], Za[4], Zb[4];

#define BW_LOADC(F_, C_, Z_, tq)                                                 \
    do {                                                                         \
        const int _m = max((tq) - 2, 0);                                         \
        F_ = g_F[_m * SS + s];                                                   \
        C_ = sD[_m * 96 + tid];                                                  \
        Z_ = sZ[((_m + 2) * 3 + ch) * 33 + lane];                                \
    } while (0)

#define BW_STEP(Fv, Cv, Zv, tc)                                                  \
    do {                                                                         \
        const float fp = (Fv).x, fv = (Fv).y, fa = (Fv).z, fb = (Fv).w;          \
        const float fc = (Cv);                                                   \
        const float th   = tanh_fast(100.0f * fv);                               \
        const float spv_ = __fmaf_rn(-Df_c, th, gd * fv);                        \
        const float g_   = __fmaf_rn(Ag_c, th * th, gdmAg_c);                    \
        const float spp_ = __fmaf_rn(DT, fv, fp);                                \
        const float bdc  = __fmaf_rn(DT, fc, fb);                                \
        const float u0   = __fmaf_rn(DT, fb, fa);                                \
        const float ap   = __fmaf_rn(DT, bdc, u0) + qp;                          \
        const float bp   = g_ * bdc;                                             \
        const float w1   = g_ * fc;                                              \
        const float cpv  = __fmaf_rn(g_, w1, qv);                                \
        const float idet = rcp_fast(__fmaf_rn(ap, cpv, -bp * bp));               \
        const float cpvI = cpv * idet;                                           \
        const float bpI  = bp  * idet;                                           \
        const float apI  = ap  * idet;                                           \
        const float u1 = g_ * fb;                                                \
        const float w0 = bdc;                                                    \
        const float G00 = __fmaf_rn(u0, cpvI, -u1 * bpI);                        \
        const float G01 = __fmaf_rn(u1, apI,  -u0 * bpI);                        \
        const float G10 = __fmaf_rn(w0, cpvI, -w1 * bpI);                        \
        const float G11 = __fmaf_rn(w1, apI,  -w0 * bpI);                        \
        const float ds0 = c0 - spp_;                                             \
        const float ds1 = c1 - spv_;                                             \
        const float ssp = __fmaf_rn(G00, ds0, __fmaf_rn(G01, ds1, fp));          \
        const float ssv = __fmaf_rn(G10, ds0, __fmaf_rn(G11, ds1, fv));          \
        const float E00 = Q00 - ap;                                              \
        const float E01 = Q01 - bp;                                              \
        const float E11 = Q11 - cpv;                                             \
        const float M00 = __fmaf_rn(G00, E00, G01 * E01);                        \
        const float M01 = __fmaf_rn(G00, E01, G01 * E11);                        \
        const float M10 = __fmaf_rn(G10, E00, G11 * E01);                        \
        const float M11 = __fmaf_rn(G10, E01, G11 * E11);                        \
        const float nQ00 = __fmaf_rn(M00, G00, __fmaf_rn(M01, G01, fa));         \
        const float nQ01 = __fmaf_rn(M00, G10, __fmaf_rn(M01, G11, fb));         \
        const float nQ11 = __fmaf_rn(M10, G10, __fmaf_rn(M11, G11, fc));         \
        c0 = ssp; c1 = ssv; Q00 = nQ00; Q01 = nQ01; Q11 = nQ11;                  \
        const float Sv = nQ00 + r;                                               \
        float e = (Zv) - ssp;                                                    \
        e = (e >  FOLD_c) ? e - TWO_PI : e;                                      \
        e = (e < -FOLD_c) ? e + TWO_PI : e;                                      \
        acc = __fmaf_rn(Sv * e, e, acc);                                         \
        sSv[(ch * NSLOT + ((tc) - 2)) * 32 + lane] = Sv;                         \
    } while (0)

    // preload: Fa[j] <- t=126-j, Fb[j] <- t=122-j
#pragma unroll
    for (int j = 0; j < 4; j++) BW_LOADC(Fa[j], Ca[j], Za[j], 126 - j);
#pragma unroll
    for (int j = 0; j < 4; j++) BW_LOADC(Fb[j], Cb[j], Zb[j], 122 - j);

    // main loop: 15 x 8 = 120 steps, t = 126 down to 7
    for (int ii = 0; ii < 15; ii++) {
        const int head_a = 126 - 8 * ii;
        const int pre_a  = head_a - 8;
#pragma unroll
        for (int j = 0; j < 4; j++) {
            const float4 Fv = Fa[j];
            const float  Cv = Ca[j], Zv = Za[j];
            BW_LOADC(Fa[j], Ca[j], Za[j], pre_a - j);
            BW_STEP(Fv, Cv, Zv, head_a - j);
        }
        const int head_b = head_a - 4;
        const int pre_b  = head_b - 8;
#pragma unroll
        for (int j = 0; j < 4; j++) {
            const float4 Fv = Fb[j];
            const float  Cv = Cb[j], Zv = Zb[j];
            BW_LOADC(Fb[j], Cb[j], Zb[j], pre_b - j);
            BW_STEP(Fv, Cv, Zv, head_b - j);
        }
    }
    // tail: t = 6,5,4,3 from bank A, t = 2 from bank B (no loads, no guards)
    BW_STEP(Fa[0], Ca[0], Za[0], 6);
    BW_STEP(Fa[1], Ca[1], Za[1], 5);
    BW_STEP(Fa[2], Ca[2], Za[2], 4);
    BW_STEP(Fa[3], Ca[3], Za[3], 3);
    BW_STEP(Fb[0], Cb[0], Zb[0], 2);
#undef BW_LOADC
#undef BW_STEP
#undef ZLDS

    // =========================== in-block combine ===========================
    __syncthreads();

    float total = acc;
    // 126*32 = 4032 = 42 * 96 exactly
    for (int idx = tid; idx < NSLOT * 32; idx += 96) {
        const int u = idx >> 5;
        const int l = idx & 31;
        total += sSv[(0 * NSLOT + u) * 32 + l]
               * sSv[(1 * NSLOT + u) * 32 + l]
               * sSv[(2 * NSLOT + u) * 32 + l];
    }
    // warp-level reduce, then 3 partials via smem
#pragma unroll
    for (int k = 16; k > 0; k >>= 1)
        total += __shfl_xor_sync(0xffffffffu, total, k);
    __syncthreads();            // all Sv reads done; reuse smem front as scratch
    if (lane == 0) sSv[ch] = total;
    __syncthreads();
    if (tid == 0) g_bsum[blockIdx.x] = sSv[0] + sSv[1] + sSv[2];
    __threadfence();
    if (tid == 0) {
        const unsigned int old = atomicInc(&g_cnt, 127u);
        sLast = (old == 127u);
    }
    __syncthreads();

    // last block: deterministic final reduce of 128 partials
    if (sLast && tid < 32) {
        __threadfence();
        double ds = 0.0;
#pragma unroll
        for (int j = 0; j < 4; j++) ds += (double)g_bsum[tid * 4 + j];
#pragma unroll
        for (int k = 16; k > 0; k >>= 1)
            ds += __shfl_xor_sync(0xffffffffu, ds, k);
        if (tid == 0) out[0] = (float)ds;
    }
}

// ---------------- launch ----------------
extern "C" void kernel_launch(void* const* d_in, const int* in_sizes, int n_in,
                              void* d_out, int out_size) {
    const float* params = nullptr;
    const float* covp   = nullptr;
    const float* init   = nullptr;
    const float* meas   = nullptr;

    for (int i = 0; i < n_in; i++) {
        if      (in_sizes[i] == 4)            params = (const float*)d_in[i];
        else if (in_sizes[i] == 7)            covp   = (const float*)d_in[i];
        else if (in_sizes[i] == BB * 6)       init   = (const float*)d_in[i];
        else if (in_sizes[i] == BB * TT * 3)  meas   = (const float*)d_in[i];
    }
    if (!params && n_in > 0) params = (const float*)d_in[0];
    if (!covp   && n_in > 1) covp   = (const float*)d_in[1];
    if (!init   && n_in > 2) init   = (const float*)d_in[2];
    if (!meas   && n_in > 3) meas   = (const float*)d_in[3];

    static int smem_set = 0;
    if (!smem_set) {
        cudaFuncSetAttribute(k_all, cudaFuncAttributeMaxDynamicSharedMemorySize,
                             SMEM_BYTES);
        smem_set = 1;
    }

    k_all<<<128, 96, SMEM_BYTES>>>(params, covp, init, meas, (float*)d_out);
}